// round 15
// baseline (speedup 1.0000x reference)
#include <cuda_runtime.h>
#include <cuda_bf16.h>
#include <cstdint>

#define B_ 8
#define L_ 2048
#define H_ 256
#define BLH (B_ * L_ * H_)

// ---------------- device scratch (no allocations allowed) ----------------
__device__ float d_E[(long long)B_ * L_ * L_];            // exp(S-60), 134 MB
__device__ float d_c[BLH];                                 // attention out fp32
__device__ float d_zacc[B_ * L_];                          // column sums (atomic)
__device__ float d_invZ[B_ * L_];
__device__ __nv_bfloat16 d_g_hi[BLH],  d_g_lo[BLH];
__device__ __nv_bfloat16 d_gT_hi[BLH], d_gT_lo[BLH];       // per-batch g^T
__device__ __nv_bfloat16 d_Wh_hi[BLH], d_Wh_lo[BLH];
__device__ __nv_bfloat16 d_WP_hi[H_ * H_], d_WP_lo[H_ * H_];
__device__ __nv_bfloat16 d_Wo_hi[H_ * 3 * H_], d_Wo_lo[H_ * 3 * H_];

// ---------------- helpers ----------------
__device__ __forceinline__ uint32_t smem_u32(const void* p) {
    uint32_t a;
    asm("{ .reg .u64 t; cvta.to.shared.u64 t, %1; cvt.u32.u64 %0, t; }"
        : "=r"(a) : "l"(p));
    return a;
}

__device__ __forceinline__ void ldsm4(uint32_t* r, uint32_t addr) {
    asm volatile("ldmatrix.sync.aligned.m8n8.x4.shared.b16 {%0,%1,%2,%3}, [%4];"
                 : "=r"(r[0]), "=r"(r[1]), "=r"(r[2]), "=r"(r[3]) : "r"(addr));
}

__device__ __forceinline__ void mma16816(float* c, const uint32_t* a, const uint32_t* b) {
    asm volatile(
        "mma.sync.aligned.m16n8k16.row.col.f32.bf16.bf16.f32 "
        "{%0,%1,%2,%3}, {%4,%5,%6,%7}, {%8,%9}, {%0,%1,%2,%3};"
        : "+f"(c[0]), "+f"(c[1]), "+f"(c[2]), "+f"(c[3])
        : "r"(a[0]), "r"(a[1]), "r"(a[2]), "r"(a[3]), "r"(b[0]), "r"(b[1]));
}

// split 8 fp32 -> 8 bf16 hi + 8 bf16 lo (packed uint4 each)
__device__ __forceinline__ void split8(float4 a, float4 b, uint4& h, uint4& l) {
    __nv_bfloat162 h0 = __floats2bfloat162_rn(a.x, a.y);
    __nv_bfloat162 h1 = __floats2bfloat162_rn(a.z, a.w);
    __nv_bfloat162 h2 = __floats2bfloat162_rn(b.x, b.y);
    __nv_bfloat162 h3 = __floats2bfloat162_rn(b.z, b.w);
    float2 f0 = __bfloat1622float2(h0), f1 = __bfloat1622float2(h1);
    float2 f2 = __bfloat1622float2(h2), f3 = __bfloat1622float2(h3);
    __nv_bfloat162 l0 = __floats2bfloat162_rn(a.x - f0.x, a.y - f0.y);
    __nv_bfloat162 l1 = __floats2bfloat162_rn(a.z - f1.x, a.w - f1.y);
    __nv_bfloat162 l2 = __floats2bfloat162_rn(b.x - f2.x, b.y - f2.y);
    __nv_bfloat162 l3 = __floats2bfloat162_rn(b.z - f3.x, b.w - f3.y);
    h = make_uint4(*(uint32_t*)&h0, *(uint32_t*)&h1, *(uint32_t*)&h2, *(uint32_t*)&h3);
    l = make_uint4(*(uint32_t*)&l0, *(uint32_t*)&l1, *(uint32_t*)&l2, *(uint32_t*)&l3);
}

// ---------------------------------------------------------------------------
// Warp-MMA NT GEMM, double-buffered with register prefetch.
// Block 128x128, BK=32, 8 warps (2M x 4N), warp tile 64x32, split-bf16 x3 MMAs.
// MODE 0: Wh = g @ WP^T               (out split bf16)
// MODE 1: E  = exp(Wh @ g^T - 60)     (out fp32 + atomic column sums)
// MODE 2: c  = [E*invZ] @ gT^T        (A built in loader, out fp32)
// MODE 3: out = relu(concat(g,c,g*c) @ Wo^T + b)
// ---------------------------------------------------------------------------
#define LDS 40                 // smem row stride in bf16 (80B, ldsm conflict-free)
#define REG_BYTES 10240        // one 128 x LDS bf16 region
#define BUF_BYTES 40960        // 4 regions (Ah, Al, Bh, Bl)
#define SMEMSZ    81920        // 2 buffers

template <int MODE>
__global__ __launch_bounds__(256) void mma_gemm(
    const float* __restrict__ g, const float* __restrict__ bout,
    float* __restrict__ out)
{
    constexpr int KDIM = (MODE == 2) ? 2048 : (MODE == 3 ? 768 : 256);
    constexpr int LDB  = (MODE == 2) ? 2048 : (MODE == 3 ? 768 : 256);
    constexpr int NCH  = KDIM / 32;

    extern __shared__ char sm[];

    const int bz  = blockIdx.z;
    const int tid = threadIdx.x;
    const int wid = tid >> 5, lid = tid & 31;
    const int wm  = wid >> 2, wn = wid & 3;          // warp grid 2 x 4
    const int mBase = blockIdx.y * 128;
    const int nBase = blockIdx.x * 128;

    const __nv_bfloat16 *Agh = nullptr, *Agl = nullptr, *Bgh = nullptr, *Bgl = nullptr;
    const float *Ef = nullptr, *iz = nullptr;
    if (MODE == 0) { Agh = d_g_hi; Agl = d_g_lo; Bgh = d_WP_hi; Bgl = d_WP_lo; }
    if (MODE == 1) {
        const long long o = (long long)bz * L_ * H_;
        Agh = d_Wh_hi + o; Agl = d_Wh_lo + o; Bgh = d_g_hi + o; Bgl = d_g_lo + o;
    }
    if (MODE == 2) {
        Ef = d_E + (long long)bz * L_ * L_;
        iz = d_invZ + bz * L_;
        const long long o = (long long)bz * H_ * L_;
        Bgh = d_gT_hi + o; Bgl = d_gT_lo + o;
    }
    if (MODE == 3) { Bgh = d_Wo_hi; Bgl = d_Wo_lo; }

    float acc[4][4][4];
    #pragma unroll
    for (int i = 0; i < 4; ++i)
        #pragma unroll
        for (int j = 0; j < 4; ++j)
            #pragma unroll
            for (int q = 0; q < 4; ++q) acc[i][j][q] = 0.f;

    // loader mapping: thread -> (row, 16-elem k half)
    const int lrow = tid >> 1;
    const int lkb  = (tid & 1) << 4;
    const int soff = (lrow * LDS + lkb) * 2;     // byte offset inside a region

    // ldmatrix per-thread byte offsets (within region)
    const uint32_t smb  = smem_u32(sm);
    const uint32_t aoff = (uint32_t)((wm * 64 + (lid & 15)) * (LDS * 2) + (lid >> 4) * 16);
    const uint32_t boff = (uint32_t)((wn * 32 + ((lid >> 4) << 3) + (lid & 7)) * (LDS * 2)
                                     + ((lid >> 3) & 1) * 16);

    uint4 rah[2], ral[2], rbh[2], rbl[2];

#define LOAD_AB(cc) do {                                                        \
    const int _k0 = (cc) * 32;                                                  \
    _Pragma("unroll")                                                           \
    for (int it = 0; it < 2; ++it) {                                            \
        const int k = lkb + it * 8;                                             \
        const long long gi = (long long)(nBase + lrow) * LDB + _k0 + k;         \
        rbh[it] = *(const uint4*)&Bgh[gi];                                      \
        rbl[it] = *(const uint4*)&Bgl[gi];                                      \
    }                                                                           \
    if (MODE == 0 || MODE == 1) {                                               \
        _Pragma("unroll")                                                       \
        for (int it = 0; it < 2; ++it) {                                        \
            const int k = lkb + it * 8;                                         \
            const long long gi = (long long)(mBase + lrow) * 256 + _k0 + k;     \
            rah[it] = *(const uint4*)&Agh[gi];                                  \
            ral[it] = *(const uint4*)&Agl[gi];                                  \
        }                                                                       \
    } else if (MODE == 2) {                                                     \
        _Pragma("unroll")                                                       \
        for (int it = 0; it < 2; ++it) {                                        \
            const int kg = _k0 + lkb + it * 8;                                  \
            const float* sp = Ef + (long long)(mBase + lrow) * 2048 + kg;       \
            float4 s0 = *(const float4*)sp;                                     \
            float4 s1 = *(const float4*)(sp + 4);                               \
            float4 z0 = *(const float4*)(iz + kg);                              \
            float4 z1 = *(const float4*)(iz + kg + 4);                          \
            s0.x *= z0.x; s0.y *= z0.y; s0.z *= z0.z; s0.w *= z0.w;             \
            s1.x *= z1.x; s1.y *= z1.y; s1.z *= z1.z; s1.w *= z1.w;             \
            split8(s0, s1, rah[it], ral[it]);                                   \
        }                                                                       \
    } else {                                                                    \
        _Pragma("unroll")                                                       \
        for (int it = 0; it < 2; ++it) {                                        \
            const int kg  = _k0 + lkb + it * 8;                                 \
            const int seg = kg >> 8, kk = kg & 255;                             \
            const long long ro = (long long)(mBase + lrow) * 256 + kk;          \
            float4 v0, v1;                                                      \
            if (seg == 0) {                                                     \
                v0 = *(const float4*)&g[ro];                                    \
                v1 = *(const float4*)&g[ro + 4];                                \
            } else if (seg == 1) {                                              \
                v0 = *(const float4*)&d_c[ro];                                  \
                v1 = *(const float4*)&d_c[ro + 4];                              \
            } else {                                                            \
                float4 g0 = *(const float4*)&g[ro];                             \
                float4 g1 = *(const float4*)&g[ro + 4];                         \
                float4 c0 = *(const float4*)&d_c[ro];                           \
                float4 c1 = *(const float4*)&d_c[ro + 4];                       \
                v0 = make_float4(g0.x*c0.x, g0.y*c0.y, g0.z*c0.z, g0.w*c0.w);   \
                v1 = make_float4(g1.x*c1.x, g1.y*c1.y, g1.z*c1.z, g1.w*c1.w);   \
            }                                                                   \
            split8(v0, v1, rah[it], ral[it]);                                   \
        }                                                                       \
    }                                                                           \
} while (0)

#define STS_AB(buf) do {                                                        \
    char* _b = sm + (buf) * BUF_BYTES + soff;                                   \
    _Pragma("unroll")                                                           \
    for (int it = 0; it < 2; ++it) {                                            \
        *(uint4*)(_b + it * 16)                 = rah[it];                      \
        *(uint4*)(_b + REG_BYTES     + it * 16) = ral[it];                      \
        *(uint4*)(_b + 2 * REG_BYTES + it * 16) = rbh[it];                      \
        *(uint4*)(_b + 3 * REG_BYTES + it * 16) = rbl[it];                      \
    }                                                                           \
} while (0)

#define MMA_PHASE(buf) do {                                                     \
    const uint32_t _sb = smb + (uint32_t)(buf) * BUF_BYTES;                     \
    _Pragma("unroll")                                                           \
    for (int ks = 0; ks < 2; ++ks) {                                            \
        uint32_t bh[4][2], bl[4][2];                                            \
        _Pragma("unroll")                                                       \
        for (int ntp = 0; ntp < 2; ++ntp) {                                     \
            uint32_t r[4];                                                      \
            ldsm4(r, _sb + 2 * REG_BYTES + boff                                 \
                     + (uint32_t)(ntp * 16 * LDS * 2 + ks * 32));               \
            bh[2*ntp][0] = r[0]; bh[2*ntp][1] = r[1];                           \
            bh[2*ntp+1][0] = r[2]; bh[2*ntp+1][1] = r[3];                       \
            ldsm4(r, _sb + 3 * REG_BYTES + boff                                 \
                     + (uint32_t)(ntp * 16 * LDS * 2 + ks * 32));               \
            bl[2*ntp][0] = r[0]; bl[2*ntp][1] = r[1];                           \
            bl[2*ntp+1][0] = r[2]; bl[2*ntp+1][1] = r[3];                       \
        }                                                                       \
        _Pragma("unroll")                                                       \
        for (int mt = 0; mt < 4; ++mt) {                                        \
            uint32_t ah[4], al[4];                                              \
            ldsm4(ah, _sb + aoff + (uint32_t)(mt * 16 * LDS * 2 + ks * 32));    \
            ldsm4(al, _sb + REG_BYTES + aoff                                    \
                      + (uint32_t)(mt * 16 * LDS * 2 + ks * 32));               \
            _Pragma("unroll")                                                   \
            for (int nt = 0; nt < 4; ++nt) {                                    \
                mma16816(acc[mt][nt], ah, bh[nt]);                              \
                mma16816(acc[mt][nt], ah, bl[nt]);                              \
                mma16816(acc[mt][nt], al, bh[nt]);                              \
            }                                                                   \
        }                                                                       \
    }                                                                           \
} while (0)

    // ---- pipelined main loop ----
    LOAD_AB(0);
    STS_AB(0);
    if (NCH > 1) LOAD_AB(1);
    __syncthreads();

    for (int c = 0; c < NCH; ++c) {
        MMA_PHASE(c & 1);
        if (c + 1 < NCH) {
            __syncthreads();
            STS_AB((c + 1) & 1);
            __syncthreads();
            if (c + 2 < NCH) LOAD_AB(c + 2);
        }
    }

#undef LOAD_AB
#undef STS_AB
#undef MMA_PHASE

    // ---- epilogue ----
    const int er = lid >> 2;            // fragment row within 8
    const int ec = (lid & 3) << 1;      // fragment col pair
    if (MODE == 1) {
        // store E = exp(S - 60) and accumulate column sums
        float* p = d_E + (long long)bz * L_ * L_;
        #pragma unroll
        for (int nt = 0; nt < 4; ++nt) {
            float cs0 = 0.f, cs1 = 0.f;
            #pragma unroll
            for (int mt = 0; mt < 4; ++mt) {
                const int row = mBase + wm * 64 + mt * 16 + er;
                const int col = nBase + wn * 32 + nt * 8 + ec;
                const float e0 = __expf(acc[mt][nt][0] - 60.f);
                const float e1 = __expf(acc[mt][nt][1] - 60.f);
                const float e2 = __expf(acc[mt][nt][2] - 60.f);
                const float e3 = __expf(acc[mt][nt][3] - 60.f);
                *(float2*)&p[(long long)row * 2048 + col]       = make_float2(e0, e1);
                *(float2*)&p[(long long)(row + 8) * 2048 + col] = make_float2(e2, e3);
                cs0 += e0 + e2;
                cs1 += e1 + e3;
            }
            #pragma unroll
            for (int off = 4; off < 32; off <<= 1) {
                cs0 += __shfl_xor_sync(0xffffffffu, cs0, off);
                cs1 += __shfl_xor_sync(0xffffffffu, cs1, off);
            }
            if (lid < 4) {
                const int col = nBase + wn * 32 + nt * 8 + lid * 2;
                atomicAdd(&d_zacc[bz * L_ + col],     cs0);
                atomicAdd(&d_zacc[bz * L_ + col + 1], cs1);
            }
        }
    } else {
        #pragma unroll
        for (int mt = 0; mt < 4; ++mt) {
            #pragma unroll
            for (int nt = 0; nt < 4; ++nt) {
                const int row = mBase + wm * 64 + mt * 16 + er;
                const int col = nBase + wn * 32 + nt * 8 + ec;
                const float* a = acc[mt][nt];
                if (MODE == 2) {
                    float* p = d_c + (long long)bz * L_ * H_;
                    *(float2*)&p[(long long)row * 256 + col]       = make_float2(a[0], a[1]);
                    *(float2*)&p[(long long)(row + 8) * 256 + col] = make_float2(a[2], a[3]);
                } else if (MODE == 0) {
                    #pragma unroll
                    for (int rr = 0; rr < 2; ++rr) {
                        const float x = a[rr * 2], y = a[rr * 2 + 1];
                        __nv_bfloat162 h = __floats2bfloat162_rn(x, y);
                        float2 f = __bfloat1622float2(h);
                        __nv_bfloat162 l = __floats2bfloat162_rn(x - f.x, y - f.y);
                        const long long o = (long long)(row + rr * 8) * 256 + col;
                        *(uint32_t*)&d_Wh_hi[o] = *(uint32_t*)&h;
                        *(uint32_t*)&d_Wh_lo[o] = *(uint32_t*)&l;
                    }
                } else {
                    const float b0 = bout[col], b1 = bout[col + 1];
                    *(float2*)&out[(long long)row * 256 + col] =
                        make_float2(fmaxf(a[0] + b0, 0.f), fmaxf(a[1] + b1, 0.f));
                    *(float2*)&out[(long long)(row + 8) * 256 + col] =
                        make_float2(fmaxf(a[2] + b0, 0.f), fmaxf(a[3] + b1, 0.f));
                }
            }
        }
    }
}

// ---------------- small helper kernels ----------------
__global__ void split_kernel(const float* __restrict__ src,
                             __nv_bfloat16* __restrict__ hi,
                             __nv_bfloat16* __restrict__ lo, int n)
{
    const int i4 = (blockIdx.x * blockDim.x + threadIdx.x) * 4;
    if (i4 < n) {
        float4 v = *(const float4*)(src + i4);
        __nv_bfloat162 h0 = __floats2bfloat162_rn(v.x, v.y);
        __nv_bfloat162 h1 = __floats2bfloat162_rn(v.z, v.w);
        float2 f0 = __bfloat1622float2(h0), f1 = __bfloat1622float2(h1);
        __nv_bfloat162 l0 = __floats2bfloat162_rn(v.x - f0.x, v.y - f0.y);
        __nv_bfloat162 l1 = __floats2bfloat162_rn(v.z - f1.x, v.w - f1.y);
        *(uint2*)(hi + i4) = make_uint2(*(uint32_t*)&h0, *(uint32_t*)&h1);
        *(uint2*)(lo + i4) = make_uint2(*(uint32_t*)&l0, *(uint32_t*)&l1);
    }
}

// g -> g_hi/g_lo (row-major) and gT_hi/gT_lo (per-batch transpose)
__global__ void split_transpose_g(const float* __restrict__ g)
{
    __shared__ float tile[32][33];
    const int b  = blockIdx.z;
    const int h0 = blockIdx.x * 32, l0 = blockIdx.y * 32;
    const int tx = threadIdx.x, ty0 = threadIdx.y;
    const long long gb = (long long)b * L_ * H_;
    #pragma unroll
    for (int p = 0; p < 4; ++p) {
        const int ty = ty0 + p * 8;
        const float v = g[gb + (long long)(l0 + ty) * H_ + h0 + tx];
        tile[ty][tx] = v;
        __nv_bfloat16 h = __float2bfloat16(v);
        const long long o = gb + (long long)(l0 + ty) * H_ + h0 + tx;
        d_g_hi[o] = h;
        d_g_lo[o] = __float2bfloat16(v - __bfloat162float(h));
    }
    __syncthreads();
    #pragma unroll
    for (int p = 0; p < 4; ++p) {
        const int ty = ty0 + p * 8;
        const float v = tile[tx][ty];
        __nv_bfloat16 h = __float2bfloat16(v);
        const long long o = gb + (long long)(h0 + ty) * L_ + l0 + tx;
        d_gT_hi[o] = h;
        d_gT_lo[o] = __float2bfloat16(v - __bfloat162float(h));
    }
}

__global__ void zero_zacc() { d_zacc[blockIdx.x * 256 + threadIdx.x] = 0.f; }

__global__ void zfinal_kernel()
{
    const int col = blockIdx.x * 256 + threadIdx.x;
    d_invZ[col] = 1.f / d_zacc[col];
}

// ---------------- launch ----------------
extern "C" void kernel_launch(void* const* d_in, const int* in_sizes, int n_in,
                              void* d_out, int out_size)
{
    (void)in_sizes; (void)n_in; (void)out_size;
    const float* g     = (const float*)d_in[0];
    const float* WP    = (const float*)d_in[1];
    const float* W_out = (const float*)d_in[2];
    const float* b_out = (const float*)d_in[3];
    float* out = (float*)d_out;

    cudaFuncSetAttribute(mma_gemm<0>, cudaFuncAttributeMaxDynamicSharedMemorySize, SMEMSZ);
    cudaFuncSetAttribute(mma_gemm<1>, cudaFuncAttributeMaxDynamicSharedMemorySize, SMEMSZ);
    cudaFuncSetAttribute(mma_gemm<2>, cudaFuncAttributeMaxDynamicSharedMemorySize, SMEMSZ);
    cudaFuncSetAttribute(mma_gemm<3>, cudaFuncAttributeMaxDynamicSharedMemorySize, SMEMSZ);

    void *pWPh, *pWPl, *pWoh, *pWol;
    cudaGetSymbolAddress(&pWPh, d_WP_hi);
    cudaGetSymbolAddress(&pWPl, d_WP_lo);
    cudaGetSymbolAddress(&pWoh, d_Wo_hi);
    cudaGetSymbolAddress(&pWol, d_Wo_lo);

    // splits / transpose / zero
    split_kernel<<<(H_ * H_ / 4 + 255) / 256, 256>>>(
        WP, (__nv_bfloat16*)pWPh, (__nv_bfloat16*)pWPl, H_ * H_);
    split_kernel<<<(H_ * 3 * H_ / 4 + 255) / 256, 256>>>(
        W_out, (__nv_bfloat16*)pWoh, (__nv_bfloat16*)pWol, H_ * 3 * H_);
    split_transpose_g<<<dim3(H_ / 32, L_ / 32, B_), dim3(32, 8)>>>(g);
    zero_zacc<<<B_ * L_ / 256, 256>>>();

    // K1: Wh = g @ WP^T             M=16384 N=256 K=256
    mma_gemm<0><<<dim3(2, 128, 1), 256, SMEMSZ>>>(g, nullptr, nullptr);
    // K2: E = exp(Wh @ g^T - 60) + column sums (per batch)  M=N=2048 K=256
    mma_gemm<1><<<dim3(16, 16, B_), 256, SMEMSZ>>>(g, nullptr, nullptr);
    // invZ
    zfinal_kernel<<<B_ * L_ / 256, 256>>>();
    // K4: c = (E*invZ) @ gT^T (per batch)   M=2048 N=256 K=2048
    mma_gemm<2><<<dim3(2, 16, B_), 256, SMEMSZ>>>(g, nullptr, nullptr);
    // K5: out = relu(concat @ Wo^T + b)     M=16384 N=256 K=768
    mma_gemm<3><<<dim3(2, 128, 1), 256, SMEMSZ>>>(g, b_out, out);
}

// round 16
// speedup vs baseline: 1.2041x; 1.2041x over previous
#include <cuda_runtime.h>
#include <cuda_bf16.h>
#include <cstdint>

#define B_ 8
#define L_ 2048
#define H_ 256
#define BLH (B_ * L_ * H_)          // 4,194,304

// ---------------- device scratch (no allocations allowed) ----------------
__device__ __align__(16) __nv_bfloat16 d_E_hi[(long long)B_ * L_ * L_];  // 67 MB
__device__ __align__(16) __nv_bfloat16 d_E_lo[(long long)B_ * L_ * L_];  // 67 MB
__device__ __align__(16) __nv_bfloat16 d_cat_hi[16384 * 768];            // 25 MB
__device__ __align__(16) __nv_bfloat16 d_cat_lo[16384 * 768];            // 25 MB
__device__ float d_zacc[B_ * L_];
__device__ float d_invZ[B_ * L_];
__device__ __align__(16) __nv_bfloat16 d_g_hi[BLH],  d_g_lo[BLH];
__device__ __align__(16) __nv_bfloat16 d_gT_hi[BLH], d_gT_lo[BLH];       // per-batch g^T
__device__ __align__(16) __nv_bfloat16 d_gTs_hi[BLH], d_gTs_lo[BLH];     // invZ-scaled g^T
__device__ __align__(16) __nv_bfloat16 d_Wh_hi[BLH], d_Wh_lo[BLH];
__device__ __align__(16) __nv_bfloat16 d_WP_hi[H_ * H_], d_WP_lo[H_ * H_];
__device__ __align__(16) __nv_bfloat16 d_Wo_hi[H_ * 3 * H_], d_Wo_lo[H_ * 3 * H_];

// ---------------- helpers ----------------
__device__ __forceinline__ uint32_t smem_u32(const void* p) {
    uint32_t a;
    asm("{ .reg .u64 t; cvta.to.shared.u64 t, %1; cvt.u32.u64 %0, t; }"
        : "=r"(a) : "l"(p));
    return a;
}

__device__ __forceinline__ void ldsm4(uint32_t* r, uint32_t addr) {
    asm volatile("ldmatrix.sync.aligned.m8n8.x4.shared.b16 {%0,%1,%2,%3}, [%4];"
                 : "=r"(r[0]), "=r"(r[1]), "=r"(r[2]), "=r"(r[3]) : "r"(addr));
}

__device__ __forceinline__ void mma16816(float* c, const uint32_t* a, const uint32_t* b) {
    asm volatile(
        "mma.sync.aligned.m16n8k16.row.col.f32.bf16.bf16.f32 "
        "{%0,%1,%2,%3}, {%4,%5,%6,%7}, {%8,%9}, {%0,%1,%2,%3};"
        : "+f"(c[0]), "+f"(c[1]), "+f"(c[2]), "+f"(c[3])
        : "r"(a[0]), "r"(a[1]), "r"(a[2]), "r"(a[3]), "r"(b[0]), "r"(b[1]));
}

#define CP16(dst, src) \
    asm volatile("cp.async.cg.shared.global [%0], [%1], 16;" \
                 :: "r"(dst), "l"(src) : "memory")

__device__ __forceinline__ void split2(float x, float y, uint32_t& h, uint32_t& l) {
    __nv_bfloat162 hh = __floats2bfloat162_rn(x, y);
    float2 f = __bfloat1622float2(hh);
    __nv_bfloat162 ll = __floats2bfloat162_rn(x - f.x, y - f.y);
    h = *(uint32_t*)&hh;
    l = *(uint32_t*)&ll;
}

// ---------------------------------------------------------------------------
// Warp-MMA NT GEMM, cp.async double-buffered (distance-2 prefetch).
// Block 128x128, BK=32, 8 warps (2M x 4N), warp tile 64x32, split-bf16 x3 MMAs.
// All operands are pre-split bf16 in global memory — uniform loader.
// MODE 0: Wh = g @ WP^T                 (epilogue: split-store Wh)
// MODE 1: E  = exp(Wh @ g^T - 60)       (epilogue: split-store E + atomic col sums)
// MODE 2: c  = E @ gTs^T                (epilogue: build cat segs 1,2 pre-split)
// MODE 3: out = relu(cat @ Wo^T + b)
// ---------------------------------------------------------------------------
#define LDS 40                 // smem row stride in bf16 (80B, ldsm conflict-free)
#define REG_BYTES 10240        // one 128 x LDS bf16 region
#define BUF_BYTES 40960        // 4 regions (Ah, Al, Bh, Bl)
#define SMEMSZ    81920        // 2 buffers

template <int MODE>
__global__ __launch_bounds__(256) void mma_gemm(
    const float* __restrict__ g, const float* __restrict__ bout,
    float* __restrict__ out)
{
    constexpr int KDIM = (MODE == 2) ? 2048 : (MODE == 3 ? 768 : 256);
    constexpr int LDA  = KDIM;
    constexpr int LDB  = KDIM;
    constexpr int NCH  = KDIM / 32;

    extern __shared__ char sm[];

    const int bz  = blockIdx.z;
    const int tid = threadIdx.x;
    const int wid = tid >> 5, lid = tid & 31;
    const int wm  = wid >> 2, wn = wid & 3;          // warp grid 2 x 4
    const int mBase = blockIdx.y * 128;
    const int nBase = blockIdx.x * 128;

    const __nv_bfloat16 *Agh, *Agl, *Bgh, *Bgl;
    if (MODE == 0) { Agh = d_g_hi; Agl = d_g_lo; Bgh = d_WP_hi; Bgl = d_WP_lo; }
    else if (MODE == 1) {
        const long long o = (long long)bz * L_ * H_;
        Agh = d_Wh_hi + o; Agl = d_Wh_lo + o; Bgh = d_g_hi + o; Bgl = d_g_lo + o;
    } else if (MODE == 2) {
        const long long oa = (long long)bz * L_ * L_;
        const long long ob = (long long)bz * H_ * L_;
        Agh = d_E_hi + oa; Agl = d_E_lo + oa; Bgh = d_gTs_hi + ob; Bgl = d_gTs_lo + ob;
    } else { Agh = d_cat_hi; Agl = d_cat_lo; Bgh = d_Wo_hi; Bgl = d_Wo_lo; }

    float acc[4][4][4];
    #pragma unroll
    for (int i = 0; i < 4; ++i)
        #pragma unroll
        for (int j = 0; j < 4; ++j)
            #pragma unroll
            for (int q = 0; q < 4; ++q) acc[i][j][q] = 0.f;

    // loader mapping: thread -> (row, 16-elem k half); 2 x 16B per region
    const int lrow = tid >> 1;
    const int lkb  = (tid & 1) << 4;
    const uint32_t soff = (uint32_t)((lrow * LDS + lkb) * 2);

    const uint32_t smb  = smem_u32(sm);
    const uint32_t aoff = (uint32_t)((wm * 64 + (lid & 15)) * (LDS * 2) + (lid >> 4) * 16);
    const uint32_t boff = (uint32_t)((wn * 32 + ((lid >> 4) << 3) + (lid & 7)) * (LDS * 2)
                                     + ((lid >> 3) & 1) * 16);

#define ISSUE(cc, buf) do {                                                     \
    const int _k0 = (cc) * 32 + lkb;                                            \
    const uint32_t _d = smb + (uint32_t)(buf) * BUF_BYTES + soff;               \
    const __nv_bfloat16* _a0 = Agh + (long long)(mBase + lrow) * LDA + _k0;     \
    const __nv_bfloat16* _a1 = Agl + (long long)(mBase + lrow) * LDA + _k0;     \
    const __nv_bfloat16* _b0 = Bgh + (long long)(nBase + lrow) * LDB + _k0;     \
    const __nv_bfloat16* _b1 = Bgl + (long long)(nBase + lrow) * LDB + _k0;     \
    CP16(_d,                      _a0); CP16(_d + 16,                 _a0 + 8); \
    CP16(_d + REG_BYTES,          _a1); CP16(_d + REG_BYTES + 16,     _a1 + 8); \
    CP16(_d + 2 * REG_BYTES,      _b0); CP16(_d + 2 * REG_BYTES + 16, _b0 + 8); \
    CP16(_d + 3 * REG_BYTES,      _b1); CP16(_d + 3 * REG_BYTES + 16, _b1 + 8); \
    asm volatile("cp.async.commit_group;" ::: "memory");                        \
} while (0)

#define MMA_PHASE(buf) do {                                                     \
    const uint32_t _sb = smb + (uint32_t)(buf) * BUF_BYTES;                     \
    _Pragma("unroll")                                                           \
    for (int ks = 0; ks < 2; ++ks) {                                            \
        uint32_t bh[4][2], bl[4][2];                                            \
        _Pragma("unroll")                                                       \
        for (int ntp = 0; ntp < 2; ++ntp) {                                     \
            uint32_t r[4];                                                      \
            ldsm4(r, _sb + 2 * REG_BYTES + boff                                 \
                     + (uint32_t)(ntp * 16 * LDS * 2 + ks * 32));               \
            bh[2*ntp][0] = r[0]; bh[2*ntp][1] = r[1];                           \
            bh[2*ntp+1][0] = r[2]; bh[2*ntp+1][1] = r[3];                       \
            ldsm4(r, _sb + 3 * REG_BYTES + boff                                 \
                     + (uint32_t)(ntp * 16 * LDS * 2 + ks * 32));               \
            bl[2*ntp][0] = r[0]; bl[2*ntp][1] = r[1];                           \
            bl[2*ntp+1][0] = r[2]; bl[2*ntp+1][1] = r[3];                       \
        }                                                                       \
        _Pragma("unroll")                                                       \
        for (int mt = 0; mt < 4; ++mt) {                                        \
            uint32_t ah[4], al[4];                                              \
            ldsm4(ah, _sb + aoff + (uint32_t)(mt * 16 * LDS * 2 + ks * 32));    \
            ldsm4(al, _sb + REG_BYTES + aoff                                    \
                      + (uint32_t)(mt * 16 * LDS * 2 + ks * 32));               \
            _Pragma("unroll")                                                   \
            for (int nt = 0; nt < 4; ++nt) {                                    \
                mma16816(acc[mt][nt], ah, bh[nt]);                              \
                mma16816(acc[mt][nt], ah, bl[nt]);                              \
                mma16816(acc[mt][nt], al, bh[nt]);                              \
            }                                                                   \
        }                                                                       \
    }                                                                           \
} while (0)

    // ---- cp.async pipelined main loop (prefetch distance 2) ----
    ISSUE(0, 0);
    if (NCH > 1) ISSUE(1, 1);

    for (int c = 0; c < NCH; ++c) {
        if (c + 1 < NCH) { asm volatile("cp.async.wait_group 1;" ::: "memory"); }
        else             { asm volatile("cp.async.wait_group 0;" ::: "memory"); }
        __syncthreads();
        MMA_PHASE(c & 1);
        if (c + 2 < NCH) {
            __syncthreads();
            ISSUE(c + 2, c & 1);
        }
    }

#undef ISSUE
#undef MMA_PHASE

    // ---- epilogue ----
    const int er = lid >> 2;            // fragment row within 8
    const int ec = (lid & 3) << 1;      // fragment col pair
    if (MODE == 1) {
        __nv_bfloat16* Eh = d_E_hi + (long long)bz * L_ * L_;
        __nv_bfloat16* El = d_E_lo + (long long)bz * L_ * L_;
        #pragma unroll
        for (int nt = 0; nt < 4; ++nt) {
            float cs0 = 0.f, cs1 = 0.f;
            #pragma unroll
            for (int mt = 0; mt < 4; ++mt) {
                const int row = mBase + wm * 64 + mt * 16 + er;
                const int col = nBase + wn * 32 + nt * 8 + ec;
                const float e0 = __expf(acc[mt][nt][0] - 60.f);
                const float e1 = __expf(acc[mt][nt][1] - 60.f);
                const float e2 = __expf(acc[mt][nt][2] - 60.f);
                const float e3 = __expf(acc[mt][nt][3] - 60.f);
                uint32_t h, l;
                split2(e0, e1, h, l);
                *(uint32_t*)&Eh[(long long)row * 2048 + col] = h;
                *(uint32_t*)&El[(long long)row * 2048 + col] = l;
                split2(e2, e3, h, l);
                *(uint32_t*)&Eh[(long long)(row + 8) * 2048 + col] = h;
                *(uint32_t*)&El[(long long)(row + 8) * 2048 + col] = l;
                cs0 += e0 + e2;
                cs1 += e1 + e3;
            }
            #pragma unroll
            for (int off = 4; off < 32; off <<= 1) {
                cs0 += __shfl_xor_sync(0xffffffffu, cs0, off);
                cs1 += __shfl_xor_sync(0xffffffffu, cs1, off);
            }
            if (lid < 4) {
                const int col = nBase + wn * 32 + nt * 8 + lid * 2;
                atomicAdd(&d_zacc[bz * L_ + col],     cs0);
                atomicAdd(&d_zacc[bz * L_ + col + 1], cs1);
            }
        }
    } else if (MODE == 2) {
        const long long rb = (long long)bz * 2048;
        #pragma unroll
        for (int mt = 0; mt < 4; ++mt) {
            #pragma unroll
            for (int nt = 0; nt < 4; ++nt) {
                const int row = mBase + wm * 64 + mt * 16 + er;
                const int col = nBase + wn * 32 + nt * 8 + ec;
                const float* a = acc[mt][nt];
                #pragma unroll
                for (int rr = 0; rr < 2; ++rr) {
                    const float c0 = a[rr * 2], c1 = a[rr * 2 + 1];
                    const long long m = rb + row + rr * 8;
                    uint32_t h, l;
                    split2(c0, c1, h, l);
                    *(uint32_t*)&d_cat_hi[m * 768 + 256 + col] = h;
                    *(uint32_t*)&d_cat_lo[m * 768 + 256 + col] = l;
                    const float2 gv = *(const float2*)&g[m * 256 + col];
                    split2(c0 * gv.x, c1 * gv.y, h, l);
                    *(uint32_t*)&d_cat_hi[m * 768 + 512 + col] = h;
                    *(uint32_t*)&d_cat_lo[m * 768 + 512 + col] = l;
                }
            }
        }
    } else {
        #pragma unroll
        for (int mt = 0; mt < 4; ++mt) {
            #pragma unroll
            for (int nt = 0; nt < 4; ++nt) {
                const int row = mBase + wm * 64 + mt * 16 + er;
                const int col = nBase + wn * 32 + nt * 8 + ec;
                const float* a = acc[mt][nt];
                if (MODE == 0) {
                    #pragma unroll
                    for (int rr = 0; rr < 2; ++rr) {
                        uint32_t h, l;
                        split2(a[rr * 2], a[rr * 2 + 1], h, l);
                        const long long o = (long long)(row + rr * 8) * 256 + col;
                        *(uint32_t*)&d_Wh_hi[o] = h;
                        *(uint32_t*)&d_Wh_lo[o] = l;
                    }
                } else {
                    const float b0 = bout[col], b1 = bout[col + 1];
                    *(float2*)&out[(long long)row * 256 + col] =
                        make_float2(fmaxf(a[0] + b0, 0.f), fmaxf(a[1] + b1, 0.f));
                    *(float2*)&out[(long long)(row + 8) * 256 + col] =
                        make_float2(fmaxf(a[2] + b0, 0.f), fmaxf(a[3] + b1, 0.f));
                }
            }
        }
    }
}

// ---------------- small helper kernels ----------------
__global__ void split_kernel(const float* __restrict__ src,
                             __nv_bfloat16* __restrict__ hi,
                             __nv_bfloat16* __restrict__ lo, int n)
{
    const int i4 = (blockIdx.x * blockDim.x + threadIdx.x) * 4;
    if (i4 < n) {
        float4 v = *(const float4*)(src + i4);
        uint32_t h0, l0, h1, l1;
        split2(v.x, v.y, h0, l0);
        split2(v.z, v.w, h1, l1);
        *(uint2*)(hi + i4) = make_uint2(h0, h1);
        *(uint2*)(lo + i4) = make_uint2(l0, l1);
    }
}

// g -> g_hi/g_lo + cat seg0 (row-major) and gT_hi/gT_lo (per-batch transpose)
__global__ void split_transpose_g(const float* __restrict__ g)
{
    __shared__ float tile[32][33];
    const int b  = blockIdx.z;
    const int h0 = blockIdx.x * 32, l0 = blockIdx.y * 32;
    const int tx = threadIdx.x, ty0 = threadIdx.y;
    const long long gb = (long long)b * L_ * H_;
    #pragma unroll
    for (int p = 0; p < 4; ++p) {
        const int ty = ty0 + p * 8;
        const float v = g[gb + (long long)(l0 + ty) * H_ + h0 + tx];
        tile[ty][tx] = v;
        __nv_bfloat16 h = __float2bfloat16(v);
        __nv_bfloat16 l = __float2bfloat16(v - __bfloat162float(h));
        const long long o = gb + (long long)(l0 + ty) * H_ + h0 + tx;
        d_g_hi[o] = h;
        d_g_lo[o] = l;
        const long long m = (long long)b * L_ + l0 + ty;
        d_cat_hi[m * 768 + h0 + tx] = h;
        d_cat_lo[m * 768 + h0 + tx] = l;
    }
    __syncthreads();
    #pragma unroll
    for (int p = 0; p < 4; ++p) {
        const int ty = ty0 + p * 8;
        const float v = tile[tx][ty];
        __nv_bfloat16 h = __float2bfloat16(v);
        const long long o = gb + (long long)(h0 + ty) * L_ + l0 + tx;
        d_gT_hi[o] = h;
        d_gT_lo[o] = __float2bfloat16(v - __bfloat162float(h));
    }
}

// gTs = split(invZ[j] * (gT_hi + gT_lo)), 8 elements per thread along L
__global__ void scale_gT_kernel()
{
    const long long i8 = ((long long)blockIdx.x * 256 + threadIdx.x) * 8;
    const int b = (int)(i8 >> 19);            // / (H*L = 524288)
    const int l = (int)(i8 & (L_ - 1));
    const float* zp = &d_invZ[b * L_ + l];
    uint4 hv = *(const uint4*)&d_gT_hi[i8];
    uint4 lv = *(const uint4*)&d_gT_lo[i8];
    const uint32_t* hp = &hv.x;
    const uint32_t* lp = &lv.x;
    uint32_t ho[4], lo[4];
    #pragma unroll
    for (int k = 0; k < 4; ++k) {
        __nv_bfloat162 hb = *(__nv_bfloat162*)&hp[k];
        __nv_bfloat162 lb = *(__nv_bfloat162*)&lp[k];
        float2 fh = __bfloat1622float2(hb);
        float2 fl = __bfloat1622float2(lb);
        split2((fh.x + fl.x) * zp[k * 2], (fh.y + fl.y) * zp[k * 2 + 1], ho[k], lo[k]);
    }
    *(uint4*)&d_gTs_hi[i8] = make_uint4(ho[0], ho[1], ho[2], ho[3]);
    *(uint4*)&d_gTs_lo[i8] = make_uint4(lo[0], lo[1], lo[2], lo[3]);
}

__global__ void zero_zacc() { d_zacc[blockIdx.x * 256 + threadIdx.x] = 0.f; }

__global__ void zfinal_kernel()
{
    const int col = blockIdx.x * 256 + threadIdx.x;
    d_invZ[col] = 1.f / d_zacc[col];
}

// ---------------- launch ----------------
extern "C" void kernel_launch(void* const* d_in, const int* in_sizes, int n_in,
                              void* d_out, int out_size)
{
    (void)in_sizes; (void)n_in; (void)out_size;
    const float* g     = (const float*)d_in[0];
    const float* WP    = (const float*)d_in[1];
    const float* W_out = (const float*)d_in[2];
    const float* b_out = (const float*)d_in[3];
    float* out = (float*)d_out;

    cudaFuncSetAttribute(mma_gemm<0>, cudaFuncAttributeMaxDynamicSharedMemorySize, SMEMSZ);
    cudaFuncSetAttribute(mma_gemm<1>, cudaFuncAttributeMaxDynamicSharedMemorySize, SMEMSZ);
    cudaFuncSetAttribute(mma_gemm<2>, cudaFuncAttributeMaxDynamicSharedMemorySize, SMEMSZ);
    cudaFuncSetAttribute(mma_gemm<3>, cudaFuncAttributeMaxDynamicSharedMemorySize, SMEMSZ);

    void *pWPh, *pWPl, *pWoh, *pWol;
    cudaGetSymbolAddress(&pWPh, d_WP_hi);
    cudaGetSymbolAddress(&pWPl, d_WP_lo);
    cudaGetSymbolAddress(&pWoh, d_Wo_hi);
    cudaGetSymbolAddress(&pWol, d_Wo_lo);

    // weight splits / g split+transpose (+cat seg0) / zero accumulators
    split_kernel<<<(H_ * H_ / 4 + 255) / 256, 256>>>(
        WP, (__nv_bfloat16*)pWPh, (__nv_bfloat16*)pWPl, H_ * H_);
    split_kernel<<<(H_ * 3 * H_ / 4 + 255) / 256, 256>>>(
        W_out, (__nv_bfloat16*)pWoh, (__nv_bfloat16*)pWol, H_ * 3 * H_);
    split_transpose_g<<<dim3(H_ / 32, L_ / 32, B_), dim3(32, 8)>>>(g);
    zero_zacc<<<B_ * L_ / 256, 256>>>();

    // K1: Wh = g @ WP^T              M=16384 N=256 K=256
    mma_gemm<0><<<dim3(2, 128, 1), 256, SMEMSZ>>>(g, nullptr, nullptr);
    // K2: E = exp(Wh @ g^T - 60), split-stored + column sums (per batch)
    mma_gemm<1><<<dim3(16, 16, B_), 256, SMEMSZ>>>(g, nullptr, nullptr);
    // invZ, then fold into gT
    zfinal_kernel<<<B_ * L_ / 256, 256>>>();
    scale_gT_kernel<<<BLH / 8 / 256, 256>>>();
    // K4: c = E @ gTs^T (per batch), epilogue builds cat segs 1,2
    mma_gemm<2><<<dim3(2, 16, B_), 256, SMEMSZ>>>(g, nullptr, nullptr);
    // K5: out = relu(cat @ Wo^T + b)  M=16384 N=256 K=768
    mma_gemm<3><<<dim3(2, 128, 1), 256, SMEMSZ>>>(g, b_out, out);
}

// round 17
// speedup vs baseline: 1.2786x; 1.0619x over previous
#include <cuda_runtime.h>
#include <cuda_bf16.h>
#include <cstdint>

#define B_ 8
#define L_ 2048
#define H_ 256
#define BLH (B_ * L_ * H_)          // 4,194,304

// ---------------- device scratch (no allocations allowed) ----------------
__device__ __align__(16) __nv_bfloat16 d_E_hi[(long long)B_ * L_ * L_];  // 67 MB
__device__ __align__(16) __nv_bfloat16 d_E_lo[(long long)B_ * L_ * L_];  // 67 MB
__device__ __align__(16) __nv_bfloat16 d_cat_hi[16384 * 768];            // 25 MB
__device__ __align__(16) __nv_bfloat16 d_cat_lo[16384 * 768];            // 25 MB
__device__ float d_zacc[B_ * L_];
__device__ float d_invZ[B_ * L_];
__device__ __align__(16) __nv_bfloat16 d_g_hi[BLH],  d_g_lo[BLH];
__device__ __align__(16) __nv_bfloat16 d_gT_hi[BLH], d_gT_lo[BLH];       // per-batch g^T
__device__ __align__(16) __nv_bfloat16 d_gTs_hi[BLH], d_gTs_lo[BLH];     // invZ-scaled g^T
__device__ __align__(16) __nv_bfloat16 d_Wh_hi[BLH], d_Wh_lo[BLH];
__device__ __align__(16) __nv_bfloat16 d_WP_hi[H_ * H_], d_WP_lo[H_ * H_];
__device__ __align__(16) __nv_bfloat16 d_Wo_hi[H_ * 3 * H_], d_Wo_lo[H_ * 3 * H_];

// ---------------- helpers ----------------
__device__ __forceinline__ uint32_t smem_u32(const void* p) {
    uint32_t a;
    asm("{ .reg .u64 t; cvta.to.shared.u64 t, %1; cvt.u32.u64 %0, t; }"
        : "=r"(a) : "l"(p));
    return a;
}

__device__ __forceinline__ void ldsm4(uint32_t* r, uint32_t addr) {
    asm volatile("ldmatrix.sync.aligned.m8n8.x4.shared.b16 {%0,%1,%2,%3}, [%4];"
                 : "=r"(r[0]), "=r"(r[1]), "=r"(r[2]), "=r"(r[3]) : "r"(addr));
}

__device__ __forceinline__ void mma16816(float* c, const uint32_t* a, const uint32_t* b) {
    asm volatile(
        "mma.sync.aligned.m16n8k16.row.col.f32.bf16.bf16.f32 "
        "{%0,%1,%2,%3}, {%4,%5,%6,%7}, {%8,%9}, {%0,%1,%2,%3};"
        : "+f"(c[0]), "+f"(c[1]), "+f"(c[2]), "+f"(c[3])
        : "r"(a[0]), "r"(a[1]), "r"(a[2]), "r"(a[3]), "r"(b[0]), "r"(b[1]));
}

#define CP16(dst, src) \
    asm volatile("cp.async.cg.shared.global [%0], [%1], 16;" \
                 :: "r"(dst), "l"(src) : "memory")

__device__ __forceinline__ void split2(float x, float y, uint32_t& h, uint32_t& l) {
    __nv_bfloat162 hh = __floats2bfloat162_rn(x, y);
    float2 f = __bfloat1622float2(hh);
    __nv_bfloat162 ll = __floats2bfloat162_rn(x - f.x, y - f.y);
    h = *(uint32_t*)&hh;
    l = *(uint32_t*)&ll;
}

// ---------------------------------------------------------------------------
// Warp-MMA NT GEMM, 3-stage cp.async pipeline, ONE __syncthreads per chunk.
// Block 128x128, BK=32, 8 warps (2M x 4N), warp tile 64x32, split-bf16 x3 MMAs.
// All operands are pre-split bf16 in global memory — uniform loader.
// MODE 0: Wh = g @ WP^T                 (epilogue: split-store Wh)
// MODE 1: E  = exp(Wh @ g^T - 60)       (epilogue: split-store E + atomic col sums)
// MODE 2: c  = E @ gTs^T                (epilogue: build cat segs 1,2 pre-split)
// MODE 3: out = relu(cat @ Wo^T + b)
// ---------------------------------------------------------------------------
#define LDS 40                 // smem row stride in bf16 (80B, ldsm conflict-free)
#define REG_BYTES 10240        // one 128 x LDS bf16 region
#define BUF_BYTES 40960        // 4 regions (Ah, Al, Bh, Bl)
#define NSTAGE    3
#define SMEMSZ    (NSTAGE * BUF_BYTES)   // 122880

template <int MODE>
__global__ __launch_bounds__(256, 1) void mma_gemm(
    const float* __restrict__ g, const float* __restrict__ bout,
    float* __restrict__ out)
{
    constexpr int KDIM = (MODE == 2) ? 2048 : (MODE == 3 ? 768 : 256);
    constexpr int LDA  = KDIM;
    constexpr int LDB  = KDIM;
    constexpr int NCH  = KDIM / 32;

    extern __shared__ char sm[];

    const int bz  = blockIdx.z;
    const int tid = threadIdx.x;
    const int wid = tid >> 5, lid = tid & 31;
    const int wm  = wid >> 2, wn = wid & 3;          // warp grid 2 x 4
    const int mBase = blockIdx.y * 128;
    const int nBase = blockIdx.x * 128;

    const __nv_bfloat16 *Agh, *Agl, *Bgh, *Bgl;
    if (MODE == 0) { Agh = d_g_hi; Agl = d_g_lo; Bgh = d_WP_hi; Bgl = d_WP_lo; }
    else if (MODE == 1) {
        const long long o = (long long)bz * L_ * H_;
        Agh = d_Wh_hi + o; Agl = d_Wh_lo + o; Bgh = d_g_hi + o; Bgl = d_g_lo + o;
    } else if (MODE == 2) {
        const long long oa = (long long)bz * L_ * L_;
        const long long ob = (long long)bz * H_ * L_;
        Agh = d_E_hi + oa; Agl = d_E_lo + oa; Bgh = d_gTs_hi + ob; Bgl = d_gTs_lo + ob;
    } else { Agh = d_cat_hi; Agl = d_cat_lo; Bgh = d_Wo_hi; Bgl = d_Wo_lo; }

    float acc[4][4][4];
    #pragma unroll
    for (int i = 0; i < 4; ++i)
        #pragma unroll
        for (int j = 0; j < 4; ++j)
            #pragma unroll
            for (int q = 0; q < 4; ++q) acc[i][j][q] = 0.f;

    // loader mapping: thread -> (row, 16-elem k half); 2 x 16B per region
    const int lrow = tid >> 1;
    const int lkb  = (tid & 1) << 4;
    const uint32_t soff = (uint32_t)((lrow * LDS + lkb) * 2);

    const uint32_t smb  = smem_u32(sm);
    const uint32_t aoff = (uint32_t)((wm * 64 + (lid & 15)) * (LDS * 2) + (lid >> 4) * 16);
    const uint32_t boff = (uint32_t)((wn * 32 + ((lid >> 4) << 3) + (lid & 7)) * (LDS * 2)
                                     + ((lid >> 3) & 1) * 16);

#define ISSUE(cc, buf) do {                                                     \
    const int _k0 = (cc) * 32 + lkb;                                            \
    const uint32_t _d = smb + (uint32_t)(buf) * BUF_BYTES + soff;               \
    const __nv_bfloat16* _a0 = Agh + (long long)(mBase + lrow) * LDA + _k0;     \
    const __nv_bfloat16* _a1 = Agl + (long long)(mBase + lrow) * LDA + _k0;     \
    const __nv_bfloat16* _b0 = Bgh + (long long)(nBase + lrow) * LDB + _k0;     \
    const __nv_bfloat16* _b1 = Bgl + (long long)(nBase + lrow) * LDB + _k0;     \
    CP16(_d,                      _a0); CP16(_d + 16,                 _a0 + 8); \
    CP16(_d + REG_BYTES,          _a1); CP16(_d + REG_BYTES + 16,     _a1 + 8); \
    CP16(_d + 2 * REG_BYTES,      _b0); CP16(_d + 2 * REG_BYTES + 16, _b0 + 8); \
    CP16(_d + 3 * REG_BYTES,      _b1); CP16(_d + 3 * REG_BYTES + 16, _b1 + 8); \
    asm volatile("cp.async.commit_group;" ::: "memory");                        \
} while (0)

#define MMA_PHASE(buf) do {                                                     \
    const uint32_t _sb = smb + (uint32_t)(buf) * BUF_BYTES;                     \
    _Pragma("unroll")                                                           \
    for (int ks = 0; ks < 2; ++ks) {                                            \
        uint32_t bh[4][2], bl[4][2];                                            \
        _Pragma("unroll")                                                       \
        for (int ntp = 0; ntp < 2; ++ntp) {                                     \
            uint32_t r[4];                                                      \
            ldsm4(r, _sb + 2 * REG_BYTES + boff                                 \
                     + (uint32_t)(ntp * 16 * LDS * 2 + ks * 32));               \
            bh[2*ntp][0] = r[0]; bh[2*ntp][1] = r[1];                           \
            bh[2*ntp+1][0] = r[2]; bh[2*ntp+1][1] = r[3];                       \
            ldsm4(r, _sb + 3 * REG_BYTES + boff                                 \
                     + (uint32_t)(ntp * 16 * LDS * 2 + ks * 32));               \
            bl[2*ntp][0] = r[0]; bl[2*ntp][1] = r[1];                           \
            bl[2*ntp+1][0] = r[2]; bl[2*ntp+1][1] = r[3];                       \
        }                                                                       \
        _Pragma("unroll")                                                       \
        for (int mt = 0; mt < 4; ++mt) {                                        \
            uint32_t ah[4], al[4];                                              \
            ldsm4(ah, _sb + aoff + (uint32_t)(mt * 16 * LDS * 2 + ks * 32));    \
            ldsm4(al, _sb + REG_BYTES + aoff                                    \
                      + (uint32_t)(mt * 16 * LDS * 2 + ks * 32));               \
            _Pragma("unroll")                                                   \
            for (int nt = 0; nt < 4; ++nt) {                                    \
                mma16816(acc[mt][nt], ah, bh[nt]);                              \
                mma16816(acc[mt][nt], ah, bl[nt]);                              \
                mma16816(acc[mt][nt], al, bh[nt]);                              \
            }                                                                   \
        }                                                                       \
    }                                                                           \
} while (0)

    // ---- 3-stage cp.async pipelined main loop (one sync per chunk) ----
    // Invariant: ISSUE(c+2) writes stage (c+2)%3, which was last READ during
    // MMA(c-1); every warp passed the chunk-c barrier (after its MMA(c-1)),
    // so no second barrier is needed before the store.
    ISSUE(0, 0);
    if (NCH > 1) ISSUE(1, 1);

    for (int c = 0; c < NCH; ++c) {
        if (c + 1 < NCH) { asm volatile("cp.async.wait_group 1;" ::: "memory"); }
        else             { asm volatile("cp.async.wait_group 0;" ::: "memory"); }
        __syncthreads();
        MMA_PHASE(c % NSTAGE);
        if (c + 2 < NCH) ISSUE(c + 2, (c + 2) % NSTAGE);
    }

#undef ISSUE
#undef MMA_PHASE

    // ---- epilogue ----
    const int er = lid >> 2;            // fragment row within 8
    const int ec = (lid & 3) << 1;      // fragment col pair
    if (MODE == 1) {
        __nv_bfloat16* Eh = d_E_hi + (long long)bz * L_ * L_;
        __nv_bfloat16* El = d_E_lo + (long long)bz * L_ * L_;
        #pragma unroll
        for (int nt = 0; nt < 4; ++nt) {
            float cs0 = 0.f, cs1 = 0.f;
            #pragma unroll
            for (int mt = 0; mt < 4; ++mt) {
                const int row = mBase + wm * 64 + mt * 16 + er;
                const int col = nBase + wn * 32 + nt * 8 + ec;
                const float e0 = __expf(acc[mt][nt][0] - 60.f);
                const float e1 = __expf(acc[mt][nt][1] - 60.f);
                const float e2 = __expf(acc[mt][nt][2] - 60.f);
                const float e3 = __expf(acc[mt][nt][3] - 60.f);
                uint32_t h, l;
                split2(e0, e1, h, l);
                *(uint32_t*)&Eh[(long long)row * 2048 + col] = h;
                *(uint32_t*)&El[(long long)row * 2048 + col] = l;
                split2(e2, e3, h, l);
                *(uint32_t*)&Eh[(long long)(row + 8) * 2048 + col] = h;
                *(uint32_t*)&El[(long long)(row + 8) * 2048 + col] = l;
                cs0 += e0 + e2;
                cs1 += e1 + e3;
            }
            #pragma unroll
            for (int off = 4; off < 32; off <<= 1) {
                cs0 += __shfl_xor_sync(0xffffffffu, cs0, off);
                cs1 += __shfl_xor_sync(0xffffffffu, cs1, off);
            }
            if (lid < 4) {
                const int col = nBase + wn * 32 + nt * 8 + lid * 2;
                atomicAdd(&d_zacc[bz * L_ + col],     cs0);
                atomicAdd(&d_zacc[bz * L_ + col + 1], cs1);
            }
        }
    } else if (MODE == 2) {
        const long long rb = (long long)bz * 2048;
        #pragma unroll
        for (int mt = 0; mt < 4; ++mt) {
            #pragma unroll
            for (int nt = 0; nt < 4; ++nt) {
                const int row = mBase + wm * 64 + mt * 16 + er;
                const int col = nBase + wn * 32 + nt * 8 + ec;
                const float* a = acc[mt][nt];
                #pragma unroll
                for (int rr = 0; rr < 2; ++rr) {
                    const float c0 = a[rr * 2], c1 = a[rr * 2 + 1];
                    const long long m = rb + row + rr * 8;
                    uint32_t h, l;
                    split2(c0, c1, h, l);
                    *(uint32_t*)&d_cat_hi[m * 768 + 256 + col] = h;
                    *(uint32_t*)&d_cat_lo[m * 768 + 256 + col] = l;
                    const float2 gv = *(const float2*)&g[m * 256 + col];
                    split2(c0 * gv.x, c1 * gv.y, h, l);
                    *(uint32_t*)&d_cat_hi[m * 768 + 512 + col] = h;
                    *(uint32_t*)&d_cat_lo[m * 768 + 512 + col] = l;
                }
            }
        }
    } else {
        #pragma unroll
        for (int mt = 0; mt < 4; ++mt) {
            #pragma unroll
            for (int nt = 0; nt < 4; ++nt) {
                const int row = mBase + wm * 64 + mt * 16 + er;
                const int col = nBase + wn * 32 + nt * 8 + ec;
                const float* a = acc[mt][nt];
                if (MODE == 0) {
                    #pragma unroll
                    for (int rr = 0; rr < 2; ++rr) {
                        uint32_t h, l;
                        split2(a[rr * 2], a[rr * 2 + 1], h, l);
                        const long long o = (long long)(row + rr * 8) * 256 + col;
                        *(uint32_t*)&d_Wh_hi[o] = h;
                        *(uint32_t*)&d_Wh_lo[o] = l;
                    }
                } else {
                    const float b0 = bout[col], b1 = bout[col + 1];
                    *(float2*)&out[(long long)row * 256 + col] =
                        make_float2(fmaxf(a[0] + b0, 0.f), fmaxf(a[1] + b1, 0.f));
                    *(float2*)&out[(long long)(row + 8) * 256 + col] =
                        make_float2(fmaxf(a[2] + b0, 0.f), fmaxf(a[3] + b1, 0.f));
                }
            }
        }
    }
}

// ---------------- small helper kernels ----------------
__global__ void split_kernel(const float* __restrict__ src,
                             __nv_bfloat16* __restrict__ hi,
                             __nv_bfloat16* __restrict__ lo, int n)
{
    const int i4 = (blockIdx.x * blockDim.x + threadIdx.x) * 4;
    if (i4 < n) {
        float4 v = *(const float4*)(src + i4);
        uint32_t h0, l0, h1, l1;
        split2(v.x, v.y, h0, l0);
        split2(v.z, v.w, h1, l1);
        *(uint2*)(hi + i4) = make_uint2(h0, h1);
        *(uint2*)(lo + i4) = make_uint2(l0, l1);
    }
}

// g -> g_hi/g_lo + cat seg0 (row-major) and gT_hi/gT_lo (per-batch transpose)
// Also zeroes d_zacc (blocks with blockIdx.x == 0).
__global__ void split_transpose_g(const float* __restrict__ g)
{
    __shared__ float tile[32][33];
    const int b  = blockIdx.z;
    const int h0 = blockIdx.x * 32, l0 = blockIdx.y * 32;
    const int tx = threadIdx.x, ty0 = threadIdx.y;
    const long long gb = (long long)b * L_ * H_;
    if (blockIdx.x == 0 && ty0 == 0)
        d_zacc[b * L_ + l0 + tx] = 0.f;
    #pragma unroll
    for (int p = 0; p < 4; ++p) {
        const int ty = ty0 + p * 8;
        const float v = g[gb + (long long)(l0 + ty) * H_ + h0 + tx];
        tile[ty][tx] = v;
        __nv_bfloat16 h = __float2bfloat16(v);
        __nv_bfloat16 l = __float2bfloat16(v - __bfloat162float(h));
        const long long o = gb + (long long)(l0 + ty) * H_ + h0 + tx;
        d_g_hi[o] = h;
        d_g_lo[o] = l;
        const long long m = (long long)b * L_ + l0 + ty;
        d_cat_hi[m * 768 + h0 + tx] = h;
        d_cat_lo[m * 768 + h0 + tx] = l;
    }
    __syncthreads();
    #pragma unroll
    for (int p = 0; p < 4; ++p) {
        const int ty = ty0 + p * 8;
        const float v = tile[tx][ty];
        __nv_bfloat16 h = __float2bfloat16(v);
        const long long o = gb + (long long)(h0 + ty) * L_ + l0 + tx;
        d_gT_hi[o] = h;
        d_gT_lo[o] = __float2bfloat16(v - __bfloat162float(h));
    }
}

// gTs = split(invZ[j] * (gT_hi + gT_lo)), 8 elements per thread along L
__global__ void scale_gT_kernel()
{
    const long long i8 = ((long long)blockIdx.x * 256 + threadIdx.x) * 8;
    const int b = (int)(i8 >> 19);            // / (H*L = 524288)
    const int l = (int)(i8 & (L_ - 1));
    const float* zp = &d_invZ[b * L_ + l];
    uint4 hv = *(const uint4*)&d_gT_hi[i8];
    uint4 lv = *(const uint4*)&d_gT_lo[i8];
    const uint32_t* hp = &hv.x;
    const uint32_t* lp = &lv.x;
    uint32_t ho[4], lo[4];
    #pragma unroll
    for (int k = 0; k < 4; ++k) {
        __nv_bfloat162 hb = *(__nv_bfloat162*)&hp[k];
        __nv_bfloat162 lb = *(__nv_bfloat162*)&lp[k];
        float2 fh = __bfloat1622float2(hb);
        float2 fl = __bfloat1622float2(lb);
        split2((fh.x + fl.x) * zp[k * 2], (fh.y + fl.y) * zp[k * 2 + 1], ho[k], lo[k]);
    }
    *(uint4*)&d_gTs_hi[i8] = make_uint4(ho[0], ho[1], ho[2], ho[3]);
    *(uint4*)&d_gTs_lo[i8] = make_uint4(lo[0], lo[1], lo[2], lo[3]);
}

__global__ void zfinal_kernel()
{
    const int col = blockIdx.x * 256 + threadIdx.x;
    d_invZ[col] = 1.f / d_zacc[col];
}

// ---------------- launch ----------------
extern "C" void kernel_launch(void* const* d_in, const int* in_sizes, int n_in,
                              void* d_out, int out_size)
{
    (void)in_sizes; (void)n_in; (void)out_size;
    const float* g     = (const float*)d_in[0];
    const float* WP    = (const float*)d_in[1];
    const float* W_out = (const float*)d_in[2];
    const float* b_out = (const float*)d_in[3];
    float* out = (float*)d_out;

    cudaFuncSetAttribute(mma_gemm<0>, cudaFuncAttributeMaxDynamicSharedMemorySize, SMEMSZ);
    cudaFuncSetAttribute(mma_gemm<1>, cudaFuncAttributeMaxDynamicSharedMemorySize, SMEMSZ);
    cudaFuncSetAttribute(mma_gemm<2>, cudaFuncAttributeMaxDynamicSharedMemorySize, SMEMSZ);
    cudaFuncSetAttribute(mma_gemm<3>, cudaFuncAttributeMaxDynamicSharedMemorySize, SMEMSZ);

    void *pWPh, *pWPl, *pWoh, *pWol;
    cudaGetSymbolAddress(&pWPh, d_WP_hi);
    cudaGetSymbolAddress(&pWPl, d_WP_lo);
    cudaGetSymbolAddress(&pWoh, d_Wo_hi);
    cudaGetSymbolAddress(&pWol, d_Wo_lo);

    // weight splits / g split+transpose (+cat seg0, +zacc zero)
    split_kernel<<<(H_ * H_ / 4 + 255) / 256, 256>>>(
        WP, (__nv_bfloat16*)pWPh, (__nv_bfloat16*)pWPl, H_ * H_);
    split_kernel<<<(H_ * 3 * H_ / 4 + 255) / 256, 256>>>(
        W_out, (__nv_bfloat16*)pWoh, (__nv_bfloat16*)pWol, H_ * 3 * H_);
    split_transpose_g<<<dim3(H_ / 32, L_ / 32, B_), dim3(32, 8)>>>(g);

    // K1: Wh = g @ WP^T              M=16384 N=256 K=256
    mma_gemm<0><<<dim3(2, 128, 1), 256, SMEMSZ>>>(g, nullptr, nullptr);
    // K2: E = exp(Wh @ g^T - 60), split-stored + column sums (per batch)
    mma_gemm<1><<<dim3(16, 16, B_), 256, SMEMSZ>>>(g, nullptr, nullptr);
    // invZ, then fold into gT
    zfinal_kernel<<<B_ * L_ / 256, 256>>>();
    scale_gT_kernel<<<BLH / 8 / 256, 256>>>();
    // K4: c = E @ gTs^T (per batch), epilogue builds cat segs 1,2
    mma_gemm<2><<<dim3(2, 16, B_), 256, SMEMSZ>>>(g, nullptr, nullptr);
    // K5: out = relu(cat @ Wo^T + b)  M=16384 N=256 K=768
    mma_gemm<3><<<dim3(2, 128, 1), 256, SMEMSZ>>>(g, b_out, out);
}